// round 2
// baseline (speedup 1.0000x reference)
#include <cuda_runtime.h>
#include <math.h>

#define NCLS 19
#define MCOMP 5
#define KCOMP 95          // NCLS * MCOMP
#define AF 64
#define LOG2PI_F 1.8378770664093453f
#define HF 256
#define WF 256

typedef unsigned long long u64;

// ---------------- device scratch (no allocs allowed) ----------------
__device__ float g_Q[KCOMP * AF];      // 1/var
__device__ float g_QL[KCOMP * AF];     // loc / var
__device__ float g_CKp[KCOMP];         // -0.5*(A*log2pi + log_det + sum(l^2 q))
__device__ float g_MT[NCLS * AF];      // l2-normalized memory means
__device__ float g_LDR[NCLS];          // log(class_target/class_sourse)
__device__ float g_blockCe[4096];
__device__ int   g_blockCnt[4096];

// ---------------- packed f32x2 helpers (Blackwell FFMA2 path) -------
__device__ __forceinline__ u64 pk2(float lo, float hi) {
    u64 r; asm("mov.b64 %0,{%1,%2};" : "=l"(r) : "f"(lo), "f"(hi)); return r;
}
__device__ __forceinline__ void upk2(u64 v, float& lo, float& hi) {
    asm("mov.b64 {%0,%1},%2;" : "=f"(lo), "=f"(hi) : "l"(v));
}
__device__ __forceinline__ u64 fma2_(u64 a, u64 b, u64 c) {
    u64 d; asm("fma.rn.f32x2 %0,%1,%2,%3;" : "=l"(d) : "l"(a), "l"(b), "l"(c)); return d;
}
__device__ __forceinline__ u64 mul2_(u64 a, u64 b) {
    u64 d; asm("mul.rn.f32x2 %0,%1,%2;" : "=l"(d) : "l"(a), "l"(b)); return d;
}

// ---------------- prep: one block per component / class --------------
__global__ __launch_bounds__(64) void prep_kernel(
        const float* __restrict__ cov,
        const float* __restrict__ mean,
        const float* __restrict__ tmem,
        const float* __restrict__ ct,
        const float* __restrict__ cs) {
    __shared__ float red[64], red2[64];
    const int t = threadIdx.x;
    const int bk = blockIdx.x;

    if (bk < KCOMP) {
        // per-GMM-component constants
        const float s = cov[bk * AF + t];
        const float l = mean[bk * AF + t];
        const float q = 1.0f / (s * s);
        g_Q [bk * AF + t] = q;
        g_QL[bk * AF + t] = l * q;
        red [t] = logf(s);
        red2[t] = l * l * q;
        __syncthreads();
        #pragma unroll
        for (int st = 32; st > 0; st >>= 1) {
            if (t < st) { red[t] += red[t + st]; red2[t] += red2[t + st]; }
            __syncthreads();
        }
        if (t == 0)
            g_CKp[bk] = -0.5f * (AF * LOG2PI_F + 2.f * red[0] + red2[0]);
    } else {
        // per-class: normalized memory mean + log class ratio
        const int c = bk - KCOMP;
        const float* p = tmem + ((size_t)(c * AF + t)) * 100;
        float s = 0.f;
        for (int i = 0; i < 100; i++) s += p[i];
        s *= 0.01f;
        red[t] = s * s;
        __syncthreads();
        #pragma unroll
        for (int st = 32; st > 0; st >>= 1) {
            if (t < st) red[t] += red[t + st];
            __syncthreads();
        }
        const float n = fmaxf(sqrtf(red[0]), 1e-12f);
        g_MT[c * AF + t] = s / n;
        if (t == 0) {
            float r = ct[c] / cs[c];
            if (isnan(r)) r = 0.f;      // nan_to_num
            g_LDR[c] = logf(r);
        }
    }
}

// ---------------- main: one thread per feature pixel -----------------
__global__ __launch_bounds__(256) void main_kernel(
    const float* __restrict__ feat,
    const int*   __restrict__ mask,
    const float* __restrict__ mean) {
    extern __shared__ float smem[];
    float* sQ   = smem;                      // 6080
    float* sQL  = sQ   + KCOMP * AF;         // 6080
    float* sL   = sQL  + KCOMP * AF;         // 6080
    float* sMT  = sL   + KCOMP * AF;         // 1216
    float* sCKp = sMT  + NCLS * AF;          // 96 (padded)
    float* sLDR = sCKp + 96;                 // 32 (padded)
    float* sRed = sLDR + 32;                 // 256
    int*   sRedI = (int*)(sRed + 256);       // 256

    const int tid = threadIdx.x;

    // cooperative param load (vectorized; later reads are warp-broadcast)
    for (int i = tid; i < (KCOMP * AF) / 4; i += 256) {
        ((float4*)sQ )[i] = ((const float4*)g_Q )[i];
        ((float4*)sQL)[i] = ((const float4*)g_QL)[i];
        ((float4*)sL )[i] = ((const float4*)mean)[i];   // loc reshape == mean layout
    }
    for (int i = tid; i < (NCLS * AF) / 4; i += 256)
        ((float4*)sMT)[i] = ((const float4*)g_MT)[i];
    if (tid < KCOMP) sCKp[tid] = g_CKp[tid];
    if (tid < NCLS)  sLDR[tid] = g_LDR[tid];
    __syncthreads();

    const int pix = blockIdx.x * 256 + tid;
    const int w = pix & (WF - 1);
    const int h = (pix >> 8) & (HF - 1);
    const int b = pix >> 16;

    // ---- validity from 4x4 mask block: valid <=> some non-ignore class count >= 12
    const int* mb = mask + ((size_t)b << 20) + (size_t)(h << 2) * 1024 + (w << 2);
    bool valid = false;
    {
        int lab[16];
        #pragma unroll
        for (int r = 0; r < 4; r++) {
            int4 v = *(const int4*)(mb + (size_t)r * 1024);
            lab[r * 4 + 0] = v.x; lab[r * 4 + 1] = v.y;
            lab[r * 4 + 2] = v.z; lab[r * 4 + 3] = v.w;
        }
        #pragma unroll
        for (int i = 0; i < 16; i++) {
            int cnt = 0;
            #pragma unroll
            for (int j = 0; j < 16; j++) cnt += (lab[j] == lab[i]);
            if (lab[i] != 255 && cnt >= 12) valid = true;
        }
    }

    // ---- load feature vector (coalesced across w), pack channel pairs, L2-normalize
    const float* fb = feat + ((size_t)b * AF * (HF * WF) + (size_t)h * WF + w);
    u64 x[AF / 2];
    u64 nacc = 0ull;
    #pragma unroll
    for (int j = 0; j < AF / 2; j++) {
        float lo = fb[(size_t)(2 * j)     * (HF * WF)];
        float hi = fb[(size_t)(2 * j + 1) * (HF * WF)];
        x[j] = pk2(lo, hi);
        nacc = fma2_(x[j], x[j], nacc);
    }
    float nlo, nhi; upk2(nacc, nlo, nhi);
    float inv = 1.f / fmaxf(sqrtf(nlo + nhi), 1e-12f);
    const u64 inv2 = pk2(inv, inv);
    u64 x2[AF / 2];
    #pragma unroll
    for (int j = 0; j < AF / 2; j++) {
        x[j]  = mul2_(x[j], inv2);
        x2[j] = mul2_(x[j], x[j]);
    }

    // ---- fused pseudo-label + CE, streaming over classes
    float bestL = -1e30f;
    float gm = -1e30f, Z = 0.f, glab = 0.f;   // streaming log-softmax over classes

    #pragma unroll 1
    for (int c = 0; c < NCLS; c++) {
        // sim logit: x . mean_target[c]
        const ulonglong2* mt = (const ulonglong2*)(sMT + c * AF);
        u64 sacc = 0ull;
        #pragma unroll
        for (int i = 0; i < AF / 4; i++) {
            ulonglong2 mv = mt[i];
            sacc = fma2_(x[2 * i],     mv.x, sacc);
            sacc = fma2_(x[2 * i + 1], mv.y, sacc);
        }
        float slo, shi; upk2(sacc, slo, shi);
        const float simlog = slo + shi;

        float lps[MCOMP];
        float lmx = -1e30f;
        #pragma unroll
        for (int m = 0; m < MCOMP; m++) {
            const int k = c * MCOMP + m;
            const ulonglong2* qp  = (const ulonglong2*)(sQ  + k * AF);
            const ulonglong2* qlp = (const ulonglong2*)(sQL + k * AF);
            const ulonglong2* lp_ = (const ulonglong2*)(sL  + k * AF);
            u64 aQ = 0ull, aQL = 0ull, aL = 0ull;
            #pragma unroll
            for (int i = 0; i < AF / 4; i++) {
                ulonglong2 qv  = qp[i];
                ulonglong2 qlv = qlp[i];
                ulonglong2 lv  = lp_[i];
                aQ  = fma2_(x2[2 * i],     qv.x,  aQ);
                aQ  = fma2_(x2[2 * i + 1], qv.y,  aQ);
                aQL = fma2_(x[2 * i],      qlv.x, aQL);
                aQL = fma2_(x[2 * i + 1],  qlv.y, aQL);
                aL  = fma2_(x[2 * i],      lv.x,  aL);
                aL  = fma2_(x[2 * i + 1],  lv.y,  aL);
            }
            float alo, ahi;
            upk2(aQ, alo, ahi);  const float qx2 = alo + ahi;
            upk2(aQL, alo, ahi); const float qlx = alo + ahi;
            upk2(aL, alo, ahi);  const float dotl = alo + ahi;
            lps[m] = sCKp[k] + qlx - 0.5f * qx2;   // diagonal-Gaussian log-prob
            lmx = fmaxf(lmx, dotl);
        }
        // logsumexp over M
        float mmax = lps[0];
        #pragma unroll
        for (int m = 1; m < MCOMP; m++) mmax = fmaxf(mmax, lps[m]);
        float msum = 0.f;
        #pragma unroll
        for (int m = 0; m < MCOMP; m++) msum += __expf(lps[m] - mmax);

        const float L = sLDR[c] + simlog + mmax + __logf(msum);
        const float g = lmx * 0.01f;            // logits_max = max_m (f.loc)/TEMP
        if (g > gm) { Z = Z * __expf(gm - g) + 1.f; gm = g; }
        else        { Z += __expf(g - gm); }
        if (L > bestL) { bestL = L; glab = g; } // first-max semantics (strict >)
    }

    const float ce = valid ? (gm + __logf(Z) - glab) : 0.f;
    const int   v  = valid ? 1 : 0;

    // deterministic in-block tree reduction
    sRed[tid] = ce; sRedI[tid] = v;
    __syncthreads();
    #pragma unroll
    for (int s = 128; s > 0; s >>= 1) {
        if (tid < s) { sRed[tid] += sRed[tid + s]; sRedI[tid] += sRedI[tid + s]; }
        __syncthreads();
    }
    if (tid == 0) {
        g_blockCe[blockIdx.x]  = sRed[0];
        g_blockCnt[blockIdx.x] = sRedI[0];
    }
}

// ---------------- finalize: deterministic partial reduction ----------
__global__ void finalize_kernel(float* __restrict__ out, int nblocks) {
    __shared__ float sf[256];
    __shared__ int   si[256];
    int tid = threadIdx.x;
    float s = 0.f; int c = 0;
    for (int i = tid; i < nblocks; i += 256) { s += g_blockCe[i]; c += g_blockCnt[i]; }
    sf[tid] = s; si[tid] = c;
    __syncthreads();
    #pragma unroll
    for (int st = 128; st > 0; st >>= 1) {
        if (tid < st) { sf[tid] += sf[tid + st]; si[tid] += si[tid + st]; }
        __syncthreads();
    }
    if (tid == 0) out[0] = sf[0] / fmaxf((float)si[0], 1.0f);
}

// ---------------- launch --------------------------------------------
extern "C" void kernel_launch(void* const* d_in, const int* in_sizes, int n_in,
                              void* d_out, int out_size) {
    const float* feat = (const float*)d_in[0];
    const int*   mask = (const int*)d_in[1];
    const float* mean = (const float*)d_in[2];
    const float* cov  = (const float*)d_in[3];
    const float* tmem = (const float*)d_in[4];
    const float* ct   = (const float*)d_in[5];
    const float* cs   = (const float*)d_in[6];

    const int B = in_sizes[0] / (AF * HF * WF);
    const int npix = B * HF * WF;
    const int nblocks = npix / 256;

    const size_t smem_bytes =
        (size_t)(KCOMP * AF * 3 + NCLS * AF + 96 + 32 + 256) * sizeof(float)
        + 256 * sizeof(int);

    cudaFuncSetAttribute(main_kernel,
                         cudaFuncAttributeMaxDynamicSharedMemorySize,
                         (int)smem_bytes);

    prep_kernel<<<KCOMP + NCLS, 64>>>(cov, mean, tmem, ct, cs);
    main_kernel<<<nblocks, 256, smem_bytes>>>(feat, mask, mean);
    finalize_kernel<<<1, 256>>>((float*)d_out, nblocks);
}

// round 3
// speedup vs baseline: 1.2888x; 1.2888x over previous
#include <cuda_runtime.h>
#include <math.h>

#define NCLS 19
#define MCOMP 5
#define KCOMP 95          // NCLS * MCOMP
#define AF 64
#define LOG2PI_F 1.8378770664093453f
#define HF 256
#define WF 256
#define TPB 128           // threads per block (occupancy: 2 blocks/SM)

typedef unsigned long long u64;

// ---------------- device scratch (no allocs allowed) ----------------
__device__ float g_Q[KCOMP * AF];      // 1/var
__device__ float g_QL[KCOMP * AF];     // loc / var
__device__ float g_CKp[KCOMP];         // -0.5*(A*log2pi + log_det + sum(l^2 q))
__device__ float g_MT[NCLS * AF];      // l2-normalized memory means
__device__ float g_LDR[NCLS];          // log(class_target/class_sourse)
__device__ float g_blockCe[4096];
__device__ int   g_blockCnt[4096];

// ---------------- packed f32x2 helpers (Blackwell FFMA2 path) -------
__device__ __forceinline__ u64 pk2(float lo, float hi) {
    u64 r; asm("mov.b64 %0,{%1,%2};" : "=l"(r) : "f"(lo), "f"(hi)); return r;
}
__device__ __forceinline__ void upk2(u64 v, float& lo, float& hi) {
    asm("mov.b64 {%0,%1},%2;" : "=f"(lo), "=f"(hi) : "l"(v));
}
__device__ __forceinline__ u64 fma2_(u64 a, u64 b, u64 c) {
    u64 d; asm("fma.rn.f32x2 %0,%1,%2,%3;" : "=l"(d) : "l"(a), "l"(b), "l"(c)); return d;
}
__device__ __forceinline__ u64 mul2_(u64 a, u64 b) {
    u64 d; asm("mul.rn.f32x2 %0,%1,%2;" : "=l"(d) : "l"(a), "l"(b)); return d;
}

// ---------------- prep: one block per component / class --------------
__global__ __launch_bounds__(64) void prep_kernel(
        const float* __restrict__ cov,
        const float* __restrict__ mean,
        const float* __restrict__ tmem,
        const float* __restrict__ ct,
        const float* __restrict__ cs) {
    __shared__ float red[64], red2[64];
    const int t = threadIdx.x;
    const int bk = blockIdx.x;

    if (bk < KCOMP) {
        const float s = cov[bk * AF + t];
        const float l = mean[bk * AF + t];
        const float q = 1.0f / (s * s);
        g_Q [bk * AF + t] = q;
        g_QL[bk * AF + t] = l * q;
        red [t] = logf(s);
        red2[t] = l * l * q;
        __syncthreads();
        #pragma unroll
        for (int st = 32; st > 0; st >>= 1) {
            if (t < st) { red[t] += red[t + st]; red2[t] += red2[t + st]; }
            __syncthreads();
        }
        if (t == 0)
            g_CKp[bk] = -0.5f * (AF * LOG2PI_F + 2.f * red[0] + red2[0]);
    } else {
        const int c = bk - KCOMP;
        const float* p = tmem + ((size_t)(c * AF + t)) * 100;
        float s = 0.f;
        for (int i = 0; i < 100; i++) s += p[i];
        s *= 0.01f;
        red[t] = s * s;
        __syncthreads();
        #pragma unroll
        for (int st = 32; st > 0; st >>= 1) {
            if (t < st) red[t] += red[t + st];
            __syncthreads();
        }
        const float n = fmaxf(sqrtf(red[0]), 1e-12f);
        g_MT[c * AF + t] = s / n;
        if (t == 0) {
            float r = ct[c] / cs[c];
            if (isnan(r)) r = 0.f;      // nan_to_num
            g_LDR[c] = logf(r);
        }
    }
}

// ---------------- main: one thread per feature pixel -----------------
__global__ __launch_bounds__(TPB, 2) void main_kernel(
    const float* __restrict__ feat,
    const int*   __restrict__ mask,
    const float* __restrict__ mean) {
    extern __shared__ float smem[];
    float* sQ   = smem;                      // 6080
    float* sQL  = sQ   + KCOMP * AF;         // 6080
    float* sL   = sQL  + KCOMP * AF;         // 6080
    float* sMT  = sL   + KCOMP * AF;         // 1216
    float* sCKp = sMT  + NCLS * AF;          // 96 (padded)
    float* sLDR = sCKp + 96;                 // 32 (padded)
    float* sRed = sLDR + 32;                 // TPB
    int*   sRedI = (int*)(sRed + TPB);       // TPB

    const int tid = threadIdx.x;

    // cooperative param load (vectorized; later reads are warp-broadcast)
    for (int i = tid; i < (KCOMP * AF) / 4; i += TPB) {
        ((float4*)sQ )[i] = ((const float4*)g_Q )[i];
        ((float4*)sQL)[i] = ((const float4*)g_QL)[i];
        ((float4*)sL )[i] = ((const float4*)mean)[i];   // loc reshape == mean layout
    }
    for (int i = tid; i < (NCLS * AF) / 4; i += TPB)
        ((float4*)sMT)[i] = ((const float4*)g_MT)[i];
    if (tid < KCOMP) sCKp[tid] = g_CKp[tid];
    if (tid < NCLS)  sLDR[tid] = g_LDR[tid];
    __syncthreads();

    const int pix = blockIdx.x * TPB + tid;
    const int w = pix & (WF - 1);
    const int h = (pix >> 8) & (HF - 1);
    const int b = pix >> 16;

    // ---- validity from 4x4 mask block: valid <=> some non-ignore class count >= 12
    const int* mb = mask + ((size_t)b << 20) + (size_t)(h << 2) * 1024 + (w << 2);
    bool valid = false;
    {
        int lab[16];
        #pragma unroll
        for (int r = 0; r < 4; r++) {
            int4 v = *(const int4*)(mb + (size_t)r * 1024);
            lab[r * 4 + 0] = v.x; lab[r * 4 + 1] = v.y;
            lab[r * 4 + 2] = v.z; lab[r * 4 + 3] = v.w;
        }
        #pragma unroll
        for (int i = 0; i < 16; i++) {
            int cnt = 0;
            #pragma unroll
            for (int j = 0; j < 16; j++) cnt += (lab[j] == lab[i]);
            if (lab[i] != 255 && cnt >= 12) valid = true;
        }
    }

    // ---- load feature vector (coalesced across w), pack channel pairs, L2-normalize
    const float* fb = feat + ((size_t)b * AF * (HF * WF) + (size_t)h * WF + w);
    u64 x[AF / 2];
    u64 nacc = 0ull;
    #pragma unroll
    for (int j = 0; j < AF / 2; j++) {
        float lo = fb[(size_t)(2 * j)     * (HF * WF)];
        float hi = fb[(size_t)(2 * j + 1) * (HF * WF)];
        x[j] = pk2(lo, hi);
        nacc = fma2_(x[j], x[j], nacc);
    }
    float nlo, nhi; upk2(nacc, nlo, nhi);
    float inv = 1.f / fmaxf(sqrtf(nlo + nhi), 1e-12f);
    const u64 inv2 = pk2(inv, inv);
    u64 x2[AF / 2];
    #pragma unroll
    for (int j = 0; j < AF / 2; j++) {
        x[j]  = mul2_(x[j], inv2);
        x2[j] = mul2_(x[j], x[j]);
    }

    // ---- fused pseudo-label + CE, streaming over classes
    float bestL = -1e30f;
    float gm = -1e30f, Z = 0.f, glab = 0.f;   // streaming log-softmax over classes

    #pragma unroll 1
    for (int c = 0; c < NCLS; c++) {
        // sim logit: x . mean_target[c]
        const ulonglong2* mt = (const ulonglong2*)(sMT + c * AF);
        u64 sacc = 0ull;
        #pragma unroll
        for (int i = 0; i < AF / 4; i++) {
            ulonglong2 mv = mt[i];
            sacc = fma2_(x[2 * i],     mv.x, sacc);
            sacc = fma2_(x[2 * i + 1], mv.y, sacc);
        }
        float slo, shi; upk2(sacc, slo, shi);
        const float simlog = slo + shi;

        float lps[MCOMP];
        float lmx = -1e30f;
        #pragma unroll
        for (int m = 0; m < MCOMP; m++) {
            const int k = c * MCOMP + m;
            const ulonglong2* qp  = (const ulonglong2*)(sQ  + k * AF);
            const ulonglong2* qlp = (const ulonglong2*)(sQL + k * AF);
            const ulonglong2* lp_ = (const ulonglong2*)(sL  + k * AF);
            u64 aQ = 0ull, aQL = 0ull, aL = 0ull;
            #pragma unroll
            for (int i = 0; i < AF / 4; i++) {
                ulonglong2 qv  = qp[i];
                ulonglong2 qlv = qlp[i];
                ulonglong2 lv  = lp_[i];
                aQ  = fma2_(x2[2 * i],     qv.x,  aQ);
                aQ  = fma2_(x2[2 * i + 1], qv.y,  aQ);
                aQL = fma2_(x[2 * i],      qlv.x, aQL);
                aQL = fma2_(x[2 * i + 1],  qlv.y, aQL);
                aL  = fma2_(x[2 * i],      lv.x,  aL);
                aL  = fma2_(x[2 * i + 1],  lv.y,  aL);
            }
            float alo, ahi;
            upk2(aQ, alo, ahi);  const float qx2 = alo + ahi;
            upk2(aQL, alo, ahi); const float qlx = alo + ahi;
            upk2(aL, alo, ahi);  const float dotl = alo + ahi;
            lps[m] = sCKp[k] + qlx - 0.5f * qx2;   // diagonal-Gaussian log-prob
            lmx = fmaxf(lmx, dotl);
        }
        // logsumexp over M
        float mmax = lps[0];
        #pragma unroll
        for (int m = 1; m < MCOMP; m++) mmax = fmaxf(mmax, lps[m]);
        float msum = 0.f;
        #pragma unroll
        for (int m = 0; m < MCOMP; m++) msum += __expf(lps[m] - mmax);

        const float L = sLDR[c] + simlog + mmax + __logf(msum);
        const float g = lmx * 0.01f;            // logits_max = max_m (f.loc)/TEMP
        if (g > gm) { Z = Z * __expf(gm - g) + 1.f; gm = g; }
        else        { Z += __expf(g - gm); }
        if (L > bestL) { bestL = L; glab = g; } // first-max semantics (strict >)
    }

    const float ce = valid ? (gm + __logf(Z) - glab) : 0.f;
    const int   v  = valid ? 1 : 0;

    // deterministic in-block tree reduction
    sRed[tid] = ce; sRedI[tid] = v;
    __syncthreads();
    #pragma unroll
    for (int s = TPB / 2; s > 0; s >>= 1) {
        if (tid < s) { sRed[tid] += sRed[tid + s]; sRedI[tid] += sRedI[tid + s]; }
        __syncthreads();
    }
    if (tid == 0) {
        g_blockCe[blockIdx.x]  = sRed[0];
        g_blockCnt[blockIdx.x] = sRedI[0];
    }
}

// ---------------- finalize: deterministic partial reduction ----------
__global__ void finalize_kernel(float* __restrict__ out, int nblocks) {
    __shared__ float sf[256];
    __shared__ int   si[256];
    int tid = threadIdx.x;
    float s = 0.f; int c = 0;
    for (int i = tid; i < nblocks; i += 256) { s += g_blockCe[i]; c += g_blockCnt[i]; }
    sf[tid] = s; si[tid] = c;
    __syncthreads();
    #pragma unroll
    for (int st = 128; st > 0; st >>= 1) {
        if (tid < st) { sf[tid] += sf[tid + st]; si[tid] += si[tid + st]; }
        __syncthreads();
    }
    if (tid == 0) out[0] = sf[0] / fmaxf((float)si[0], 1.0f);
}

// ---------------- launch --------------------------------------------
extern "C" void kernel_launch(void* const* d_in, const int* in_sizes, int n_in,
                              void* d_out, int out_size) {
    const float* feat = (const float*)d_in[0];
    const int*   mask = (const int*)d_in[1];
    const float* mean = (const float*)d_in[2];
    const float* cov  = (const float*)d_in[3];
    const float* tmem = (const float*)d_in[4];
    const float* ct   = (const float*)d_in[5];
    const float* cs   = (const float*)d_in[6];

    const int B = in_sizes[0] / (AF * HF * WF);
    const int npix = B * HF * WF;
    const int nblocks = npix / TPB;

    const size_t smem_bytes =
        (size_t)(KCOMP * AF * 3 + NCLS * AF + 96 + 32 + TPB) * sizeof(float)
        + TPB * sizeof(int);

    cudaFuncSetAttribute(main_kernel,
                         cudaFuncAttributeMaxDynamicSharedMemorySize,
                         (int)smem_bytes);

    prep_kernel<<<KCOMP + NCLS, 64>>>(cov, mean, tmem, ct, cs);
    main_kernel<<<nblocks, TPB, smem_bytes>>>(feat, mask, mean);
    finalize_kernel<<<1, 256>>>((float*)d_out, nblocks);
}

// round 5
// speedup vs baseline: 4.2879x; 3.3271x over previous
#include <cuda_runtime.h>
#include <cuda_bf16.h>
#include <math.h>
#include <stdint.h>

#define NCLS 19
#define MCOMP 5
#define KCOMP 95
#define AF 64
#define LOG2PI_F 1.8378770664093453f
#define HF 256
#define WF 256
#define TPB 256
#define KDIM 128          // [x_hat | x_hat^2]
#define CSTRIDE 12        // B cols per class: [maha*5 | l*5 | mt | pad]
#define NCOLS 240         // 10 pairs * 24 (cols 228..239 zero)
#define NPAIRS 10
#define ROWB 272          // bytes per A/B smem row (136 bf16: 128 data + pad)

typedef uint32_t u32;

// ---------------- device scratch (no allocs allowed) ----------------
__device__ float g_Q[KCOMP * AF];
__device__ float g_QL[KCOMP * AF];
__device__ float g_CKp[KCOMP];
__device__ float g_MT[NCLS * AF];
__device__ float g_LDR[NCLS];
__device__ __nv_bfloat16 g_B[NCOLS * KDIM];
__device__ float g_blockCe[4096];
__device__ int   g_blockCnt[4096];

// ---------------- smem layout (bytes) ----------------
#define A_OFF    0                         // 256 x 272  = 69632
#define B_OFF    69632                     // 240 x 272  = 65280
#define DX_OFF   134912                    // 8 warps x 32 x 104 = 26624
#define CKP_OFF  161536                    // 96 floats
#define LDR_OFF  161920                    // 32 floats
#define RED_OFF  162048                    // 256 floats
#define REDI_OFF 163072                    // 256 ints
#define SMEM_TOTAL 164096

// ---------------- PTX helpers ----------------
__device__ __forceinline__ u32 smem_u32(const void* p) {
    u32 a;
    asm("{ .reg .u64 t; cvta.to.shared.u64 t, %1; cvt.u32.u64 %0, t; }"
        : "=r"(a) : "l"(p));
    return a;
}
#define LDMX4(r, a) \
    asm volatile("ldmatrix.sync.aligned.m8n8.x4.shared.b16 {%0,%1,%2,%3}, [%4];" \
        : "=r"((r)[0]), "=r"((r)[1]), "=r"((r)[2]), "=r"((r)[3]) : "r"(a))
#define LDMX2(r0, r1, a) \
    asm volatile("ldmatrix.sync.aligned.m8n8.x2.shared.b16 {%0,%1}, [%2];" \
        : "=r"(r0), "=r"(r1) : "r"(a))
#define MMA(c, a, b0_, b1_) \
    asm volatile("mma.sync.aligned.m16n8k16.row.col.f32.bf16.bf16.f32 " \
        "{%0,%1,%2,%3}, {%4,%5,%6,%7}, {%8,%9}, {%0,%1,%2,%3};" \
        : "+f"((c)[0]), "+f"((c)[1]), "+f"((c)[2]), "+f"((c)[3]) \
        : "r"((a)[0]), "r"((a)[1]), "r"((a)[2]), "r"((a)[3]), "r"(b0_), "r"(b1_))

__device__ __forceinline__ u32 pkbf(float lo, float hi) {
    return (u32)__bfloat16_as_ushort(__float2bfloat16_rn(lo)) |
           ((u32)__bfloat16_as_ushort(__float2bfloat16_rn(hi)) << 16);
}

// ---------------- prep: per-component / per-class constants ----------
__global__ __launch_bounds__(64) void prep_kernel(
        const float* __restrict__ cov,
        const float* __restrict__ mean,
        const float* __restrict__ tmem,
        const float* __restrict__ ct,
        const float* __restrict__ cs) {
    __shared__ float red[64], red2[64];
    const int t = threadIdx.x;
    const int bk = blockIdx.x;

    if (bk < KCOMP) {
        const float s = cov[bk * AF + t];
        const float l = mean[bk * AF + t];
        const float q = 1.0f / (s * s);
        g_Q [bk * AF + t] = q;
        g_QL[bk * AF + t] = l * q;
        red [t] = logf(s);
        red2[t] = l * l * q;
        __syncthreads();
        #pragma unroll
        for (int st = 32; st > 0; st >>= 1) {
            if (t < st) { red[t] += red[t + st]; red2[t] += red2[t + st]; }
            __syncthreads();
        }
        if (t == 0)
            g_CKp[bk] = -0.5f * (AF * LOG2PI_F + 2.f * red[0] + red2[0]);
    } else {
        const int c = bk - KCOMP;
        const float* p = tmem + ((size_t)(c * AF + t)) * 100;
        float s = 0.f;
        for (int i = 0; i < 100; i++) s += p[i];
        s *= 0.01f;
        red[t] = s * s;
        __syncthreads();
        #pragma unroll
        for (int st = 32; st > 0; st >>= 1) {
            if (t < st) red[t] += red[t + st];
            __syncthreads();
        }
        const float n = fmaxf(sqrtf(red[0]), 1e-12f);
        g_MT[c * AF + t] = s / n;
        if (t == 0) {
            float r = ct[c] / cs[c];
            if (isnan(r)) r = 0.f;
            g_LDR[c] = logf(r);
        }
    }
}

// ---------------- prep2: build bf16 B [NCOLS x KDIM] -----------------
// row n = 12c + j: j<5: [ql | -0.5q] (fused maha); j in 5..9: [l | 0];
//                  j==10: [mt | 0]; j==11 / n>=228: zero
__global__ void prep2_kernel(const float* __restrict__ mean) {
    const int n = blockIdx.x;
    const int k = threadIdx.x;
    float val = 0.f;
    if (n < 228) {
        const int c = n / CSTRIDE, j = n - c * CSTRIDE;
        if (j < 5) {
            val = (k < 64) ? g_QL[(c * 5 + j) * AF + k]
                           : -0.5f * g_Q[(c * 5 + j) * AF + (k - 64)];
        } else if (j < 10) {
            if (k < 64) val = mean[(c * 5 + (j - 5)) * AF + k];
        } else if (j == 10) {
            if (k < 64) val = g_MT[c * AF + k];
        }
    }
    g_B[n * KDIM + k] = __float2bfloat16_rn(val);
}

// ---------------- main: persistent HMMA GEMM + fused epilogue --------
__global__ __launch_bounds__(TPB, 1) void main_kernel(
        const float* __restrict__ feat,
        const int*   __restrict__ mask,
        int ntiles) {
    extern __shared__ char smem[];
    const u32 sb = smem_u32(smem);
    float* sCKp = (float*)(smem + CKP_OFF);
    float* sLDR = (float*)(smem + LDR_OFF);
    float* sRed = (float*)(smem + RED_OFF);
    int*   sRedI = (int*)(smem + REDI_OFF);

    const int tid = threadIdx.x;
    const int lane = tid & 31;
    const int w = tid >> 5;

    // ---- one-time: B -> smem (rows padded to 272B)
    for (int i = tid; i < NCOLS * 16; i += TPB) {
        const int row = i >> 4, u = i & 15;
        *(uint4*)(smem + B_OFF + row * ROWB + u * 16) =
            ((const uint4*)g_B)[row * 16 + u];
    }
    if (tid < KCOMP) sCKp[tid] = g_CKp[tid];
    if (tid < NCLS)  sLDR[tid] = g_LDR[tid];
    __syncthreads();

    // ---- ldmatrix lane address bases
    u32 aAddr[2];
    {
        const int rin = (lane & 7) + ((lane >> 3) & 1) * 8;
        const int k16 = (lane >> 4) & 1;
        aAddr[0] = sb + A_OFF + (u32)(32 * w + rin) * ROWB + k16 * 16;
        aAddr[1] = aAddr[0] + 16 * ROWB;
    }
    const u32 bA4 = sb + B_OFF
        + (u32)((lane & 7) + ((lane >> 4) & 1) * 8) * ROWB
        + ((lane >> 3) & 1) * 16;
    const int m15 = lane & 15;
    const u32 bA2 = sb + B_OFF + (u32)(16 + (m15 & 7)) * ROWB
        + ((m15 >> 3) & 1) * 16;

    char* dxw = smem + DX_OFF + w * 3328;
    const int r0 = lane >> 2;
    const int cb = 2 * (lane & 3);

    for (int t = blockIdx.x; t < ntiles; t += gridDim.x) {
        const int pix = t * TPB + tid;
        const int hw = pix & 65535;
        const int b = pix >> 16;

        // ---- validity: some non-ignore class with count >= 12 in 4x4 block.
        // A >=12 majority must appear among ANY 5 slots (pigeonhole).
        const int ww = pix & (WF - 1);
        const int hh = (pix >> 8) & (HF - 1);
        const int* mb = mask + ((size_t)b << 20) + (size_t)(hh << 2) * 1024 + (ww << 2);
        int valid = 0;
        {
            int lab[16];
            #pragma unroll
            for (int r = 0; r < 4; r++) {
                int4 v4 = *(const int4*)(mb + (size_t)r * 1024);
                lab[r * 4 + 0] = v4.x; lab[r * 4 + 1] = v4.y;
                lab[r * 4 + 2] = v4.z; lab[r * 4 + 3] = v4.w;
            }
            #pragma unroll
            for (int i = 0; i < 5; i++) {
                int cnt = 0;
                #pragma unroll
                for (int j = 0; j < 16; j++) cnt += (lab[j] == lab[i]);
                if (lab[i] != 255 && cnt >= 12) valid = 1;
            }
        }

        // ---- load feature (coalesced across tid), normalize in fp32
        const float* fbp = feat + ((size_t)b << 22) + hw;
        float x[AF];
        float n0 = 0.f, n1 = 0.f, n2 = 0.f, n3 = 0.f;
        #pragma unroll
        for (int a = 0; a < AF; a += 4) {
            x[a]     = fbp[(size_t)a << 16];
            x[a + 1] = fbp[(size_t)(a + 1) << 16];
            x[a + 2] = fbp[(size_t)(a + 2) << 16];
            x[a + 3] = fbp[(size_t)(a + 3) << 16];
            n0 = fmaf(x[a], x[a], n0);         n1 = fmaf(x[a + 1], x[a + 1], n1);
            n2 = fmaf(x[a + 2], x[a + 2], n2); n3 = fmaf(x[a + 3], x[a + 3], n3);
        }
        const float inv = 1.0f / fmaxf(sqrtf((n0 + n1) + (n2 + n3)), 1e-12f);

        // ---- write A row tid = [x_hat(64) | x_hat^2(64)] bf16
        __syncwarp();
        {
            char* arow = smem + A_OFF + (size_t)tid * ROWB;
            #pragma unroll
            for (int i = 0; i < 8; i++) {
                const int a = i * 8;
                float e0 = x[a] * inv,     e1 = x[a + 1] * inv;
                float e2 = x[a + 2] * inv, e3 = x[a + 3] * inv;
                float e4 = x[a + 4] * inv, e5 = x[a + 5] * inv;
                float e6 = x[a + 6] * inv, e7 = x[a + 7] * inv;
                uint4 v0, v1;
                v0.x = pkbf(e0, e1); v0.y = pkbf(e2, e3);
                v0.z = pkbf(e4, e5); v0.w = pkbf(e6, e7);
                v1.x = pkbf(e0 * e0, e1 * e1); v1.y = pkbf(e2 * e2, e3 * e3);
                v1.z = pkbf(e4 * e4, e5 * e5); v1.w = pkbf(e6 * e6, e7 * e7);
                ((uint4*)arow)[i] = v0;
                ((uint4*)arow)[8 + i] = v1;
            }
        }
        __syncwarp();

        // ---- load resident A fragments (this warp's 32 rows x K=128)
        u32 af[2][8][4];
        #pragma unroll
        for (int mt = 0; mt < 2; mt++)
            #pragma unroll
            for (int ks = 0; ks < 8; ks++)
                LDMX4(af[mt][ks], aAddr[mt] + ks * 32);

        // ---- per class-pair: 3 n-tiles GEMM + exchange + epilogue
        float gm = -1e30f, Z = 0.f, glab = 0.f, bestL = -1e30f;

        #pragma unroll 1
        for (int p = 0; p < NPAIRS; p++) {
            float cacc[24];
            #pragma unroll
            for (int i = 0; i < 24; i++) cacc[i] = 0.f;
            const u32 b4 = bA4 + (u32)p * (24 * ROWB);
            const u32 b2 = bA2 + (u32)p * (24 * ROWB);
            #pragma unroll
            for (int ks = 0; ks < 8; ks++) {
                u32 br[4], d0, d1;
                LDMX4(br, b4 + ks * 32);
                LDMX2(d0, d1, b2 + ks * 32);
                MMA(cacc + 0,  af[0][ks], br[0], br[1]);   // nt0, mt0
                MMA(cacc + 4,  af[1][ks], br[0], br[1]);   // nt0, mt1
                MMA(cacc + 8,  af[0][ks], br[2], br[3]);   // nt1, mt0
                MMA(cacc + 12, af[1][ks], br[2], br[3]);   // nt1, mt1
                MMA(cacc + 16, af[0][ks], d0, d1);         // nt2, mt0
                MMA(cacc + 20, af[1][ks], d0, d1);         // nt2, mt1
            }

            // D exchange (per-warp buffer, rows padded to 26 floats)
            __syncwarp();
            #pragma unroll
            for (int mt = 0; mt < 2; mt++)
                #pragma unroll
                for (int nt = 0; nt < 3; nt++) {
                    const float* cc = &cacc[(nt * 2 + mt) * 4];
                    *(float2*)(dxw + (r0 + mt * 16) * 104 + (nt * 8 + cb) * 4)
                        = make_float2(cc[0], cc[1]);
                    *(float2*)(dxw + (r0 + 8 + mt * 16) * 104 + (nt * 8 + cb) * 4)
                        = make_float2(cc[2], cc[3]);
                }
            __syncwarp();
            float v[24];
            {
                const char* rdx = dxw + lane * 104;
                #pragma unroll
                for (int i = 0; i < 12; i++) {
                    float2 t2 = *(const float2*)(rdx + i * 8);
                    v[2 * i] = t2.x; v[2 * i + 1] = t2.y;
                }
            }

            // epilogue: two classes of this pair (streaming, ascending c)
            #pragma unroll
            for (int cc2 = 0; cc2 < 2; cc2++) {
                const int c = 2 * p + cc2;
                if (c < NCLS) {
                    const float* vb = v + cc2 * 12;
                    float lp0 = sCKp[c * 5 + 0] + vb[0];
                    float lp1 = sCKp[c * 5 + 1] + vb[1];
                    float lp2 = sCKp[c * 5 + 2] + vb[2];
                    float lp3 = sCKp[c * 5 + 3] + vb[3];
                    float lp4 = sCKp[c * 5 + 4] + vb[4];
                    float mmax = fmaxf(fmaxf(fmaxf(lp0, lp1), fmaxf(lp2, lp3)), lp4);
                    float msum = __expf(lp0 - mmax) + __expf(lp1 - mmax)
                               + __expf(lp2 - mmax) + __expf(lp3 - mmax)
                               + __expf(lp4 - mmax);
                    float lmx = fmaxf(fmaxf(fmaxf(vb[5], vb[6]), fmaxf(vb[7], vb[8])), vb[9]);
                    const float simlog = vb[10];
                    const float L = sLDR[c] + simlog + mmax + __logf(msum);
                    const float g = lmx * 0.01f;
                    if (g > gm) { Z = Z * __expf(gm - g) + 1.f; gm = g; }
                    else        { Z += __expf(g - gm); }
                    if (L > bestL) { bestL = L; glab = g; }  // first-max (strict >)
                }
            }
        }

        const float ce = valid ? (gm + __logf(Z) - glab) : 0.f;

        // deterministic in-block tree reduction
        __syncthreads();
        sRed[tid] = ce; sRedI[tid] = valid;
        __syncthreads();
        #pragma unroll
        for (int s = TPB / 2; s > 0; s >>= 1) {
            if (tid < s) { sRed[tid] += sRed[tid + s]; sRedI[tid] += sRedI[tid + s]; }
            __syncthreads();
        }
        if (tid == 0) {
            g_blockCe[t]  = sRed[0];
            g_blockCnt[t] = sRedI[0];
        }
    }
}

// ---------------- finalize ----------------
__global__ void finalize_kernel(float* __restrict__ out, int nblocks) {
    __shared__ float sf[256];
    __shared__ int   si[256];
    int tid = threadIdx.x;
    float s = 0.f; int c = 0;
    for (int i = tid; i < nblocks; i += 256) { s += g_blockCe[i]; c += g_blockCnt[i]; }
    sf[tid] = s; si[tid] = c;
    __syncthreads();
    #pragma unroll
    for (int st = 128; st > 0; st >>= 1) {
        if (tid < st) { sf[tid] += sf[tid + st]; si[tid] += si[tid + st]; }
        __syncthreads();
    }
    if (tid == 0) out[0] = sf[0] / fmaxf((float)si[0], 1.0f);
}

// ---------------- launch ----------------
extern "C" void kernel_launch(void* const* d_in, const int* in_sizes, int n_in,
                              void* d_out, int out_size) {
    const float* feat = (const float*)d_in[0];
    const int*   mask = (const int*)d_in[1];
    const float* mean = (const float*)d_in[2];
    const float* cov  = (const float*)d_in[3];
    const float* tmem = (const float*)d_in[4];
    const float* ct   = (const float*)d_in[5];
    const float* cs   = (const float*)d_in[6];

    const int B = in_sizes[0] / (AF * HF * WF);
    const int npix = B * HF * WF;
    const int ntiles = npix / TPB;

    cudaFuncSetAttribute(main_kernel,
                         cudaFuncAttributeMaxDynamicSharedMemorySize, SMEM_TOTAL);

    prep_kernel<<<KCOMP + NCLS, 64>>>(cov, mean, tmem, ct, cs);
    prep2_kernel<<<NCOLS, KDIM>>>(mean);
    main_kernel<<<148, TPB, SMEM_TOTAL>>>(feat, mask, ntiles);
    finalize_kernel<<<1, 256>>>((float*)d_out, ntiles);
}

// round 6
// speedup vs baseline: 4.8006x; 1.1196x over previous
#include <cuda_runtime.h>
#include <cuda_bf16.h>
#include <math.h>
#include <stdint.h>

#define NCLS 19
#define MCOMP 5
#define KCOMP 95
#define AF 64
#define LOG2PI_F 1.8378770664093453f
#define HF 256
#define WF 256
#define TPB 128
#define KDIM 128          // [x_hat | x_hat^2]
#define CSTRIDE 12        // B cols per class: [maha*5 | l*5 | mt | pad]
#define NCOLS 240
#define NPAIRS 10
#define ROWB 272          // padded smem row (128 bf16 + 8 pad)
#define GRIDM 296         // 2 CTAs x 148 SMs

typedef uint32_t u32;

// ---------------- device scratch (no allocs allowed) ----------------
__device__ float g_CKp[KCOMP];
__device__ float g_LDR[NCLS];
__device__ __nv_bfloat16 g_B[NCOLS * KDIM];
__device__ float g_blockCe[8192];
__device__ int   g_blockCnt[8192];
__device__ unsigned int g_done;

// ---------------- smem layout (bytes) ----------------
#define A_OFF    0                    // 128 x 272 = 34816 (aliased by exchange)
#define B_OFF    34816                // 240 x 272 = 65280
#define CKP_OFF  100096               // 96 floats
#define LDR_OFF  100480               // 24 floats
#define SMEM_TOTAL 100576

// ---------------- PTX helpers ----------------
__device__ __forceinline__ u32 smem_u32(const void* p) {
    u32 a;
    asm("{ .reg .u64 t; cvta.to.shared.u64 t, %1; cvt.u32.u64 %0, t; }"
        : "=r"(a) : "l"(p));
    return a;
}
#define LDMX4(r, a) \
    asm volatile("ldmatrix.sync.aligned.m8n8.x4.shared.b16 {%0,%1,%2,%3}, [%4];" \
        : "=r"((r)[0]), "=r"((r)[1]), "=r"((r)[2]), "=r"((r)[3]) : "r"(a))
#define LDMX2(r0, r1, a) \
    asm volatile("ldmatrix.sync.aligned.m8n8.x2.shared.b16 {%0,%1}, [%2];" \
        : "=r"(r0), "=r"(r1) : "r"(a))
#define MMA(c, a, b0_, b1_) \
    asm volatile("mma.sync.aligned.m16n8k16.row.col.f32.bf16.bf16.f32 " \
        "{%0,%1,%2,%3}, {%4,%5,%6,%7}, {%8,%9}, {%0,%1,%2,%3};" \
        : "+f"((c)[0]), "+f"((c)[1]), "+f"((c)[2]), "+f"((c)[3]) \
        : "r"((a)[0]), "r"((a)[1]), "r"((a)[2]), "r"((a)[3]), "r"(b0_), "r"(b1_))

__device__ __forceinline__ u32 pkbf(float lo, float hi) {
    return (u32)__bfloat16_as_ushort(__float2bfloat16_rn(lo)) |
           ((u32)__bfloat16_as_ushort(__float2bfloat16_rn(hi)) << 16);
}

// ---------------- prep (fused): constants + B matrix -----------------
// blocks 0..94   : GMM component (c,j) -> B rows 12c+j (maha), 12c+5+j (l), CKp
// blocks 95..113 : class c -> B row 12c+10 (mt), 12c+11 (zero), LDR
// block 114      : zero B rows 228..239, reset g_done
__global__ __launch_bounds__(64) void prep_kernel(
        const float* __restrict__ cov,
        const float* __restrict__ mean,
        const float* __restrict__ tmem,
        const float* __restrict__ ct,
        const float* __restrict__ cs) {
    __shared__ float red[64], red2[64];
    const int t = threadIdx.x;
    const int bk = blockIdx.x;
    const __nv_bfloat16 z = __float2bfloat16_rn(0.f);

    if (bk < KCOMP) {
        const int c = bk / 5, j = bk - 5 * c;
        const float s = cov[bk * AF + t];
        const float l = mean[bk * AF + t];
        const float q = 1.0f / (s * s);
        const int n1 = (CSTRIDE * c + j) * KDIM;
        const int n2 = (CSTRIDE * c + 5 + j) * KDIM;
        g_B[n1 + t]      = __float2bfloat16_rn(l * q);
        g_B[n1 + 64 + t] = __float2bfloat16_rn(-0.5f * q);
        g_B[n2 + t]      = __float2bfloat16_rn(l);
        g_B[n2 + 64 + t] = z;
        red [t] = logf(s);
        red2[t] = l * l * q;
        __syncthreads();
        #pragma unroll
        for (int st = 32; st > 0; st >>= 1) {
            if (t < st) { red[t] += red[t + st]; red2[t] += red2[t + st]; }
            __syncthreads();
        }
        if (t == 0)
            g_CKp[bk] = -0.5f * (AF * LOG2PI_F + 2.f * red[0] + red2[0]);
    } else if (bk < KCOMP + NCLS) {
        const int c = bk - KCOMP;
        const float* p = tmem + ((size_t)(c * AF + t)) * 100;
        float s = 0.f;
        for (int i = 0; i < 100; i++) s += p[i];
        s *= 0.01f;
        red[t] = s * s;
        __syncthreads();
        #pragma unroll
        for (int st = 32; st > 0; st >>= 1) {
            if (t < st) red[t] += red[t + st];
            __syncthreads();
        }
        const float n = fmaxf(sqrtf(red[0]), 1e-12f);
        const int n1 = (CSTRIDE * c + 10) * KDIM;
        const int n2 = (CSTRIDE * c + 11) * KDIM;
        g_B[n1 + t]      = __float2bfloat16_rn(s / n);
        g_B[n1 + 64 + t] = z;
        g_B[n2 + t]      = z;
        g_B[n2 + 64 + t] = z;
        if (t == 0) {
            float r = ct[c] / cs[c];
            if (isnan(r)) r = 0.f;
            g_LDR[c] = logf(r);
        }
    } else {
        for (int i = t; i < (NCOLS - 228) * KDIM; i += 64)
            g_B[228 * KDIM + i] = z;
        if (t == 0) g_done = 0;
    }
}

// ---------------- main: persistent HMMA GEMM + fused epilogue + finalize
__global__ __launch_bounds__(TPB, 2) void main_kernel(
        const float* __restrict__ feat,
        const int*   __restrict__ mask,
        float* __restrict__ out,
        int ntiles) {
    extern __shared__ char smem[];
    const u32 sb = smem_u32(smem);
    float* sCKp = (float*)(smem + CKP_OFF);
    float* sLDR = (float*)(smem + LDR_OFF);

    const int tid = threadIdx.x;
    const int lane = tid & 31;
    const int w = tid >> 5;

    // ---- one-time: B -> smem (rows padded to 272B)
    for (int i = tid; i < NCOLS * 16; i += TPB) {
        const int row = i >> 4, u = i & 15;
        *(uint4*)(smem + B_OFF + row * ROWB + u * 16) =
            ((const uint4*)g_B)[row * 16 + u];
    }
    if (tid < KCOMP) sCKp[tid] = g_CKp[tid];
    if (tid < NCLS)  sLDR[tid] = g_LDR[tid];
    __syncthreads();

    // ---- ldmatrix lane address bases
    u32 aAddr[2];
    {
        const int rin = (lane & 7) + ((lane >> 3) & 1) * 8;
        const int k16 = (lane >> 4) & 1;
        aAddr[0] = sb + A_OFF + (u32)(32 * w + rin) * ROWB + k16 * 16;
        aAddr[1] = aAddr[0] + 16 * ROWB;
    }
    const u32 bA4 = sb + B_OFF
        + (u32)((lane & 7) + ((lane >> 4) & 1) * 8) * ROWB
        + ((lane >> 3) & 1) * 16;
    const int m15 = lane & 15;
    const u32 bA2 = sb + B_OFF + (u32)(16 + (m15 & 7)) * ROWB
        + ((m15 >> 3) & 1) * 16;

    // exchange buffer aliases this warp's (consumed) A region
    char* dxw = smem + A_OFF + w * (32 * ROWB);
    const int r0 = lane >> 2;
    const int cb = 2 * (lane & 3);

    for (int t = blockIdx.x; t < ntiles; t += gridDim.x) {
        const int pix = t * TPB + tid;
        const int hw = pix & 65535;
        const int b = pix >> 16;

        // ---- validity: some non-ignore class with count >= 12 in 4x4 block
        const int ww = pix & (WF - 1);
        const int hh = (pix >> 8) & (HF - 1);
        const int* mb = mask + ((size_t)b << 20) + (size_t)(hh << 2) * 1024 + (ww << 2);
        int valid = 0;
        {
            int lab[16];
            #pragma unroll
            for (int r = 0; r < 4; r++) {
                int4 v4 = *(const int4*)(mb + (size_t)r * 1024);
                lab[r * 4 + 0] = v4.x; lab[r * 4 + 1] = v4.y;
                lab[r * 4 + 2] = v4.z; lab[r * 4 + 3] = v4.w;
            }
            #pragma unroll
            for (int i = 0; i < 5; i++) {
                int cnt = 0;
                #pragma unroll
                for (int j = 0; j < 16; j++) cnt += (lab[j] == lab[i]);
                if (lab[i] != 255 && cnt >= 12) valid = 1;
            }
        }

        // ---- load feature (coalesced), normalize in fp32
        const float* fbp = feat + ((size_t)b << 22) + hw;
        float x[AF];
        float n0 = 0.f, n1 = 0.f, n2 = 0.f, n3 = 0.f;
        #pragma unroll
        for (int a = 0; a < AF; a += 4) {
            x[a]     = fbp[(size_t)a << 16];
            x[a + 1] = fbp[(size_t)(a + 1) << 16];
            x[a + 2] = fbp[(size_t)(a + 2) << 16];
            x[a + 3] = fbp[(size_t)(a + 3) << 16];
            n0 = fmaf(x[a], x[a], n0);         n1 = fmaf(x[a + 1], x[a + 1], n1);
            n2 = fmaf(x[a + 2], x[a + 2], n2); n3 = fmaf(x[a + 3], x[a + 3], n3);
        }
        const float inv = 1.0f / fmaxf(sqrtf((n0 + n1) + (n2 + n3)), 1e-12f);

        // ---- write A row tid = [x_hat | x_hat^2] bf16 (warp-local region)
        __syncwarp();
        {
            char* arow = smem + A_OFF + (size_t)tid * ROWB;
            #pragma unroll
            for (int i = 0; i < 8; i++) {
                const int a = i * 8;
                float e0 = x[a] * inv,     e1 = x[a + 1] * inv;
                float e2 = x[a + 2] * inv, e3 = x[a + 3] * inv;
                float e4 = x[a + 4] * inv, e5 = x[a + 5] * inv;
                float e6 = x[a + 6] * inv, e7 = x[a + 7] * inv;
                uint4 v0, v1;
                v0.x = pkbf(e0, e1); v0.y = pkbf(e2, e3);
                v0.z = pkbf(e4, e5); v0.w = pkbf(e6, e7);
                v1.x = pkbf(e0 * e0, e1 * e1); v1.y = pkbf(e2 * e2, e3 * e3);
                v1.z = pkbf(e4 * e4, e5 * e5); v1.w = pkbf(e6 * e6, e7 * e7);
                ((uint4*)arow)[i] = v0;
                ((uint4*)arow)[8 + i] = v1;
            }
        }
        __syncwarp();

        // ---- resident A fragments (warp's 32 rows x K=128)
        u32 af[2][8][4];
        #pragma unroll
        for (int mt = 0; mt < 2; mt++)
            #pragma unroll
            for (int ks = 0; ks < 8; ks++)
                LDMX4(af[mt][ks], aAddr[mt] + ks * 32);
        __syncwarp();   // A region may now be reused as exchange buffer

        // ---- per class-pair: GEMM (B prefetch pipelined) + exchange + epilogue
        float gm = -1e30f, Z = 0.f, glab = 0.f, bestL = -1e30f;

        #pragma unroll 1
        for (int p = 0; p < NPAIRS; p++) {
            float cacc[24];
            #pragma unroll
            for (int i = 0; i < 24; i++) cacc[i] = 0.f;
            const u32 b4 = bA4 + (u32)p * (24 * ROWB);
            const u32 b2 = bA2 + (u32)p * (24 * ROWB);

            u32 br[4], d0, d1;
            LDMX4(br, b4);
            LDMX2(d0, d1, b2);
            #pragma unroll
            for (int ks = 0; ks < 8; ks++) {
                u32 brn[4], dn0, dn1;
                if (ks < 7) {
                    LDMX4(brn, b4 + (ks + 1) * 32);
                    LDMX2(dn0, dn1, b2 + (ks + 1) * 32);
                }
                MMA(cacc + 0,  af[0][ks], br[0], br[1]);
                MMA(cacc + 4,  af[1][ks], br[0], br[1]);
                MMA(cacc + 8,  af[0][ks], br[2], br[3]);
                MMA(cacc + 12, af[1][ks], br[2], br[3]);
                MMA(cacc + 16, af[0][ks], d0, d1);
                MMA(cacc + 20, af[1][ks], d0, d1);
                if (ks < 7) {
                    br[0] = brn[0]; br[1] = brn[1]; br[2] = brn[2]; br[3] = brn[3];
                    d0 = dn0; d1 = dn1;
                }
            }

            // D exchange through warp-local buffer (rows 26 floats = 104B)
            __syncwarp();
            #pragma unroll
            for (int mt = 0; mt < 2; mt++)
                #pragma unroll
                for (int nt = 0; nt < 3; nt++) {
                    const float* cc = &cacc[(nt * 2 + mt) * 4];
                    *(float2*)(dxw + (r0 + mt * 16) * 104 + (nt * 8 + cb) * 4)
                        = make_float2(cc[0], cc[1]);
                    *(float2*)(dxw + (r0 + 8 + mt * 16) * 104 + (nt * 8 + cb) * 4)
                        = make_float2(cc[2], cc[3]);
                }
            __syncwarp();
            float v[24];
            {
                const char* rdx = dxw + lane * 104;
                #pragma unroll
                for (int i = 0; i < 12; i++) {
                    float2 t2 = *(const float2*)(rdx + i * 8);
                    v[2 * i] = t2.x; v[2 * i + 1] = t2.y;
                }
            }
            __syncwarp();

            // epilogue: two classes of this pair (streaming, ascending c)
            #pragma unroll
            for (int cc2 = 0; cc2 < 2; cc2++) {
                const int c = 2 * p + cc2;
                if (c < NCLS) {
                    const float* vb = v + cc2 * 12;
                    float lp0 = sCKp[c * 5 + 0] + vb[0];
                    float lp1 = sCKp[c * 5 + 1] + vb[1];
                    float lp2 = sCKp[c * 5 + 2] + vb[2];
                    float lp3 = sCKp[c * 5 + 3] + vb[3];
                    float lp4 = sCKp[c * 5 + 4] + vb[4];
                    float mmax = fmaxf(fmaxf(fmaxf(lp0, lp1), fmaxf(lp2, lp3)), lp4);
                    float msum = __expf(lp0 - mmax) + __expf(lp1 - mmax)
                               + __expf(lp2 - mmax) + __expf(lp3 - mmax)
                               + __expf(lp4 - mmax);
                    float lmx = fmaxf(fmaxf(fmaxf(vb[5], vb[6]), fmaxf(vb[7], vb[8])), vb[9]);
                    const float L = sLDR[c] + vb[10] + mmax + __logf(msum);
                    const float g = lmx * 0.01f;
                    if (g > gm) { Z = Z * __expf(gm - g) + 1.f; gm = g; }
                    else        { Z += __expf(g - gm); }
                    if (L > bestL) { bestL = L; glab = g; }   // first-max (strict >)
                }
            }
        }

        float ce = valid ? (gm + __logf(Z) - glab) : 0.f;
        int   vv = valid;

        // deterministic warp butterfly reduction -> per-warp partial
        #pragma unroll
        for (int off = 16; off > 0; off >>= 1) {
            ce += __shfl_xor_sync(0xffffffffu, ce, off);
            vv += __shfl_xor_sync(0xffffffffu, vv, off);
        }
        if (lane == 0) {
            g_blockCe[t * 4 + w]  = ce;
            g_blockCnt[t * 4 + w] = vv;
        }
    }

    // ---- fused finalize: last CTA reduces all per-warp partials
    __shared__ bool isLast;
    __shared__ float sf4[4];
    __shared__ int   si4[4];
    __threadfence();
    __syncthreads();
    if (tid == 0) {
        unsigned int o = atomicAdd(&g_done, 1u);
        isLast = (o == (unsigned int)(gridDim.x - 1));
    }
    __syncthreads();
    if (isLast) {
        __threadfence();
        const int ntot = ntiles * 4;
        float s = 0.f; int c = 0;
        for (int i = tid; i < ntot; i += TPB) {
            s += g_blockCe[i];
            c += g_blockCnt[i];
        }
        #pragma unroll
        for (int off = 16; off > 0; off >>= 1) {
            s += __shfl_xor_sync(0xffffffffu, s, off);
            c += __shfl_xor_sync(0xffffffffu, c, off);
        }
        if (lane == 0) { sf4[w] = s; si4[w] = c; }
        __syncthreads();
        if (tid == 0) {
            const float tot = ((sf4[0] + sf4[1]) + (sf4[2] + sf4[3]));
            const int   cnt = ((si4[0] + si4[1]) + (si4[2] + si4[3]));
            out[0] = tot / fmaxf((float)cnt, 1.0f);
        }
    }
}

// ---------------- launch ----------------
extern "C" void kernel_launch(void* const* d_in, const int* in_sizes, int n_in,
                              void* d_out, int out_size) {
    const float* feat = (const float*)d_in[0];
    const int*   mask = (const int*)d_in[1];
    const float* mean = (const float*)d_in[2];
    const float* cov  = (const float*)d_in[3];
    const float* tmem = (const float*)d_in[4];
    const float* ct   = (const float*)d_in[5];
    const float* cs   = (const float*)d_in[6];

    const int B = in_sizes[0] / (AF * HF * WF);
    const int npix = B * HF * WF;
    const int ntiles = npix / TPB;

    cudaFuncSetAttribute(main_kernel,
                         cudaFuncAttributeMaxDynamicSharedMemorySize, SMEM_TOTAL);

    prep_kernel<<<KCOMP + NCLS + 1, 64>>>(cov, mean, tmem, ct, cs);
    main_kernel<<<GRIDM, TPB, SMEM_TOTAL>>>(feat, mask, (float*)d_out, ntiles);
}